// round 3
// baseline (speedup 1.0000x reference)
#include <cuda_runtime.h>
#include <math.h>

#define N_MAX 10000
#define E_MAX 100000

typedef unsigned long long ull;

// Scratch (no cudaMalloc allowed)
__device__ float g_q[N_MAX * 20];         // per-node q: 8 scalar + 4*3 vector
__device__ float g_z[N_MAX];              // softmax denominator
__device__ float g_ex[E_MAX];             // per-edge exp(dot) -> later sqrt(alpha)
__device__ float g_v[(size_t)E_MAX * 40]; // per-edge v: 16 scalar + 8*3 vector

// ---- packed f32x2 helpers (sm_100+) ----
__device__ __forceinline__ ull ffma2(ull a, ull b, ull c) {
    ull d; asm("fma.rn.f32x2 %0, %1, %2, %3;" : "=l"(d) : "l"(a), "l"(b), "l"(c)); return d;
}
__device__ __forceinline__ ull fmul2(ull a, ull b) {
    ull d; asm("mul.rn.f32x2 %0, %1, %2;" : "=l"(d) : "l"(a), "l"(b)); return d;
}
__device__ __forceinline__ ull pack2(float a, float b) {
    ull r; asm("mov.b64 %0, {%1, %2};" : "=l"(r) : "f"(a), "f"(b)); return r;
}

// ---------------------------------------------------------------------------
// Kernel 0: per-node q projection, zero z and out
// ---------------------------------------------------------------------------
__global__ void __launch_bounds__(64) k_nodes(const float* __restrict__ node_ft,
                        const float* __restrict__ wqs,   // [16,8]
                        const float* __restrict__ wqv,   // [8,4]
                        float* __restrict__ out, int N)
{
    int n = blockIdx.x * blockDim.x + threadIdx.x;
    if (n >= N) return;
    const float* x = node_ft + (size_t)n * 40;
    float xs[16], xv[24];
#pragma unroll
    for (int i = 0; i < 16; i++) xs[i] = x[i];
#pragma unroll
    for (int i = 0; i < 24; i++) xv[i] = x[16 + i];

    const float s0 = 0.25f;                   // 1/sqrt(16)
    const float s1 = 0.35355339059327373f;    // 1/sqrt(8)
    float q[20];
#pragma unroll
    for (int o = 0; o < 8; o++) {
        float acc = 0.f;
#pragma unroll
        for (int i = 0; i < 16; i++) acc += xs[i] * wqs[i * 8 + o];
        q[o] = acc * s0;
    }
#pragma unroll
    for (int o = 0; o < 4; o++) {
#pragma unroll
        for (int c = 0; c < 3; c++) {
            float acc = 0.f;
#pragma unroll
            for (int i = 0; i < 8; i++) acc += xv[i * 3 + c] * wqv[i * 4 + o];
            q[8 + o * 3 + c] = acc * s1;
        }
    }
#pragma unroll
    for (int i = 0; i < 20; i++) g_q[(size_t)n * 20 + i] = q[i];
    g_z[n] = 0.f;
    float4 z4 = make_float4(0.f, 0.f, 0.f, 0.f);
#pragma unroll
    for (int i = 0; i < 10; i++)
        *reinterpret_cast<float4*>(&out[(size_t)n * 40 + i * 4]) = z4;
}

// ---------------------------------------------------------------------------
// Kernel 1: persistent per-edge main kernel.
//   grid = 148 blocks x 256 threads, 1 block/SM, W2 resident in smem.
//   Tile = 16 edges. Per tile:
//     StageA: load idx/es/sh -> smem
//     StageB: gather node_ft/q -> smem, compute hidden acts h (packed {h,h})
//     P2:     weight-gen  w = h @ W2 / sqrt(32)  via FFMA2, 8 edges x 8 cols/thr
//     P3:     warp-per-edge CG contraction -> k, v; dot; exp; atomic z
// ---------------------------------------------------------------------------

// smem float offsets
#define OFF_W2K 0        // 32*320
#define OFF_W2V 10240    // 32*640
#define OFF_W1K 30720    // 512
#define OFF_W1V 31232    // 512
#define OFF_WDS 31744    // 64
#define OFF_WDV 31808    // 16
#define OFF_H2  31824    // 16*64 ull = 2048 floats (8B aligned)
#define OFF_WK  33872    // 16*320
#define OFF_WV  38992    // 16*640
#define OFF_PF  49232    // 16*96
#define OFF_KK  50768    // 16*20
#define OFF_ES  51088    // 16*16
#define OFF_SH4 51344    // 16*4
#define OFF_NF  51408    // 16*40
#define OFF_QR  52048    // 16*20
#define OFF_IDX 52368    // 16*2 ints
#define SMEM_FLOATS 52400
#define SMEM_BYTES (SMEM_FLOATS * 4)

__global__ void __launch_bounds__(256, 1) k_edges(
    const float* __restrict__ node_ft,
    const int* __restrict__ eidx,            // [2,E] int32
    const float* __restrict__ edge_sh,       // [E,4]
    const float* __restrict__ edge_sc,       // [E,16]
    const float* __restrict__ fck_w1,        // [16,32]
    const float* __restrict__ fck_w2,        // [32,320]
    const float* __restrict__ fcv_w1,        // [16,32]
    const float* __restrict__ fcv_w2,        // [32,640]
    const float* __restrict__ wdot_s,        // [8,8]
    const float* __restrict__ wdot_v,        // [4,4]
    int E)
{
    extern __shared__ float sm[];
    const int tid = threadIdx.x;

    // ---- startup: stage weights into smem (once per block) ----
    for (int i = tid; i < 10240; i += 256) sm[OFF_W2K + i] = fck_w2[i];
    for (int i = tid; i < 20480; i += 256) sm[OFF_W2V + i] = fcv_w2[i];
    for (int i = tid; i < 512; i += 256) { sm[OFF_W1K + i] = fck_w1[i]; sm[OFF_W1V + i] = fcv_w1[i]; }
    if (tid < 64) sm[OFF_WDS + tid] = wdot_s[tid];
    if (tid < 16) sm[OFF_WDV + tid] = wdot_v[tid];
    __syncthreads();

    const int ntiles = (E + 15) >> 4;
    const float ISQ32 = 0.17677669529663687f;   // 1/sqrt(32)
    const float ISQ24 = 0.2041241452319315f;    // 1/sqrt(24)
    const float ISQ3  = 0.5773502691896258f;    // 1/sqrt(3)
    const float ISQ2  = 0.7071067811865476f;    // 1/sqrt(2)

    int* sidx = (int*)(sm + OFF_IDX);

    for (int t = blockIdx.x; t < ntiles; t += gridDim.x) {
        const int ebase = t << 4;

        // ---- Stage A: indices, edge scalars, spherical harmonics ----
        if (tid < 32) {
            int e = tid & 15, which = tid >> 4;
            int eg = min(ebase + e, E - 1);
            sidx[e * 2 + which] = eidx[(size_t)which * E + eg];
        }
        {
            int e = tid >> 4, i = tid & 15;
            int eg = min(ebase + e, E - 1);
            sm[OFF_ES + tid] = edge_sc[(size_t)eg * 16 + i];
        }
        if (tid >= 64 && tid < 128) {
            int f = tid - 64; int e = f >> 2;
            int eg = min(ebase + e, E - 1);
            sm[OFF_SH4 + f] = edge_sh[(size_t)eg * 4 + (f & 3)];
        }
        __syncthreads();

        // ---- Stage B: gather node features + q, compute hidden acts ----
        float nv0, nv1, nv2 = 0.f, qv0, qv1 = 0.f;
        {
            int f = tid;       int e = f / 40; nv0 = node_ft[(size_t)sidx[e * 2] * 40 + (f % 40)];
        }
        {
            int f = tid + 256; int e = f / 40; nv1 = node_ft[(size_t)sidx[e * 2] * 40 + (f % 40)];
        }
        if (tid < 128) {
            int f = tid + 512; int e = f / 40; nv2 = node_ft[(size_t)sidx[e * 2] * 40 + (f % 40)];
        }
        {
            int f = tid;       int e = f / 20; qv0 = g_q[(size_t)sidx[e * 2 + 1] * 20 + (f % 20)];
        }
        if (tid < 64) {
            int f = tid + 256; int e = f / 20; qv1 = g_q[(size_t)sidx[e * 2 + 1] * 20 + (f % 20)];
        }

        // hidden activations while gathers are in flight
        ull* H2 = (ull*)(sm + OFF_H2);
#pragma unroll
        for (int s = 0; s < 4; s++) {
            int task = tid + s * 256;
            int e = task >> 6, jj = task & 63;
            const float* W1 = sm + ((jj < 32) ? OFF_W1K : OFF_W1V);
            int j = jj & 31;
            const float* es = sm + OFF_ES + e * 16;
            float acc = 0.f;
#pragma unroll
            for (int i = 0; i < 16; i++) acc += es[i] * W1[i * 32 + j];
            acc *= 0.25f;                                        // 1/sqrt(16)
            float h = __fdividef(acc, 1.f + __expf(-acc));       // silu
            H2[e * 64 + jj] = pack2(h, h);
        }

        // commit gathers
        sm[OFF_NF + tid] = nv0;
        sm[OFF_NF + tid + 256] = nv1;
        if (tid < 128) sm[OFF_NF + tid + 512] = nv2;
        sm[OFF_QR + tid] = qv0;
        if (tid < 64) sm[OFF_QR + tid + 256] = qv1;
        __syncthreads();

        // ---- P2: weight generation with FFMA2 ----
        {
            const int g = tid >> 7;        // edge group 0/1 (8 edges each)
            const int ct = tid & 127;
            if (ct < 120) {
                const float* W2; float* OW; int col, ncol, hoff;
                if (ct < 40) { W2 = sm + OFF_W2K; OW = sm + OFF_WK; col = ct * 8;        ncol = 320; hoff = 0;  }
                else         { W2 = sm + OFF_W2V; OW = sm + OFF_WV; col = (ct - 40) * 8; ncol = 640; hoff = 32; }
                const ull* Hb = H2 + (g * 8) * 64 + hoff;
                ull a0[8], a1[8], a2[8], a3[8];
#pragma unroll
                for (int e = 0; e < 8; e++) { a0[e] = 0; a1[e] = 0; a2[e] = 0; a3[e] = 0; }
#pragma unroll 2
                for (int j = 0; j < 32; j++) {
                    ulonglong2 wa = *reinterpret_cast<const ulonglong2*>(W2 + (size_t)j * ncol + col);
                    ulonglong2 wb = *reinterpret_cast<const ulonglong2*>(W2 + (size_t)j * ncol + col + 4);
#pragma unroll
                    for (int e = 0; e < 8; e++) {
                        ull hh = Hb[e * 64 + j];
                        a0[e] = ffma2(hh, wa.x, a0[e]);
                        a1[e] = ffma2(hh, wa.y, a1[e]);
                        a2[e] = ffma2(hh, wb.x, a2[e]);
                        a3[e] = ffma2(hh, wb.y, a3[e]);
                    }
                }
                ull sc = pack2(ISQ32, ISQ32);
#pragma unroll
                for (int e = 0; e < 8; e++) {
                    ull* dst = (ull*)(OW + (size_t)(g * 8 + e) * ncol + col);
                    dst[0] = fmul2(a0[e], sc); dst[1] = fmul2(a1[e], sc);
                    dst[2] = fmul2(a2[e], sc); dst[3] = fmul2(a3[e], sc);
                }
            }
        }
        __syncthreads();

        // ---- P3: warp per edge (2 edges per warp) ----
        const int wid = tid >> 5, lane = tid & 31;
#pragma unroll
        for (int r = 0; r < 2; r++) {
            const int le = wid * 2 + r;
            const int eg = ebase + le;
            const bool active = (eg < E);
            const float* nf = sm + OFF_NF + le * 40;
            const float shs  = sm[OFF_SH4 + le * 4 + 0];
            const float shv0 = sm[OFF_SH4 + le * 4 + 1];
            const float shv1 = sm[OFF_SH4 + le * 4 + 2];
            const float shv2 = sm[OFF_SH4 + le * 4 + 3];
            float* P = sm + OFF_PF + le * 96;

            // build P features: XS@0(16) XV@16(24) SHS@40 SHV@41(3) PSS@44(16) PVV@60(8) PXX@68(24)
            if (lane < 16) {
                float xs = nf[lane];
                P[lane] = xs;
                P[44 + lane] = xs * shs;
            } else if (lane < 24) {
                int i = lane - 16;
                float v0 = nf[16 + i * 3 + 0];
                float v1 = nf[16 + i * 3 + 1];
                float v2 = nf[16 + i * 3 + 2];
                P[16 + i * 3 + 0] = v0; P[16 + i * 3 + 1] = v1; P[16 + i * 3 + 2] = v2;
                P[60 + i] = (v0 * shv0 + v1 * shv1 + v2 * shv2) * ISQ3;
                P[68 + i * 3 + 0] = (v1 * shv2 - v2 * shv1) * ISQ2;
                P[68 + i * 3 + 1] = (v2 * shv0 - v0 * shv2) * ISQ2;
                P[68 + i * 3 + 2] = (v0 * shv1 - v1 * shv0) * ISQ2;
            } else if (lane == 24) {
                P[40] = shs; P[41] = shv0; P[42] = shv1; P[43] = shv2;
            }
            __syncwarp();

            const float* WK = sm + OFF_WK + le * 320;
            const float* WV = sm + OFF_WV + le * 640;
            float* K = sm + OFF_KK + le * 20;

            // k_s (lanes 0..7), k_v (lanes 8..19)
            if (lane < 8) {
                int o = lane;
                float acc = 0.f;
#pragma unroll
                for (int i = 0; i < 16; i++) acc += P[44 + i] * WK[i * 8 + o];
#pragma unroll
                for (int i = 0; i < 8;  i++) acc += P[60 + i] * WK[128 + i * 8 + o];
                K[o] = acc * ISQ24;
            } else if (lane < 20) {
                int tt = lane - 8; int o = tt / 3; int c = tt % 3;
                float a = 0.f, b = 0.f, cx = 0.f;
#pragma unroll
                for (int i = 0; i < 16; i++) a  += P[i]              * WK[192 + i * 4 + o];
#pragma unroll
                for (int i = 0; i < 8;  i++) b  += P[16 + i * 3 + c] * WK[256 + i * 4 + o];
#pragma unroll
                for (int i = 0; i < 8;  i++) cx += P[68 + i * 3 + c] * WK[288 + i * 4 + o];
                K[8 + tt] = (P[41 + c] * a + P[40] * b + cx) * ISQ32;
            }

            // v_s (lanes 0..15)
            if (lane < 16) {
                int o = lane;
                float acc = 0.f;
#pragma unroll
                for (int i = 0; i < 16; i++) acc += P[44 + i] * WV[i * 16 + o];
#pragma unroll
                for (int i = 0; i < 8;  i++) acc += P[60 + i] * WV[256 + i * 16 + o];
                if (active) g_v[(size_t)eg * 40 + o] = acc * ISQ24;
            }
            // v_v: 24 comps: lanes 16..31 -> t=0..15, lanes 0..7 -> t=16..23
            {
                int tt = (lane >= 16) ? (lane - 16) : (lane + 16);
                if (tt < 24) {
                    int o = tt / 3, c = tt % 3;
                    float a = 0.f, b = 0.f, cx = 0.f;
#pragma unroll
                    for (int i = 0; i < 16; i++) a  += P[i]              * WV[384 + i * 8 + o];
#pragma unroll
                    for (int i = 0; i < 8;  i++) b  += P[16 + i * 3 + c] * WV[512 + i * 8 + o];
#pragma unroll
                    for (int i = 0; i < 8;  i++) cx += P[68 + i * 3 + c] * WV[576 + i * 8 + o];
                    float vv = (P[41 + c] * a + P[40] * b + cx) * ISQ32;
                    if (active) g_v[(size_t)eg * 40 + 16 + tt] = vv;
                }
            }
            __syncwarp();

            // dot(q[recv], k)
            const float* qr = sm + OFF_QR + le * 20;
            const float* WDS = sm + OFF_WDS;
            const float* WDV = sm + OFF_WDV;
            float d = 0.f;
            {
                int term = lane;
                int i = term >> 3, j = term & 7;
                d += qr[i] * K[j] * WDS[i * 8 + j];
                term += 32; i = term >> 3; j = term & 7;
                d += qr[i] * K[j] * WDS[i * 8 + j];
            }
            if (lane < 16) {
                int i = lane >> 2, j = lane & 3;
                float s = qr[8 + i * 3 + 0] * K[8 + j * 3 + 0]
                        + qr[8 + i * 3 + 1] * K[8 + j * 3 + 1]
                        + qr[8 + i * 3 + 2] * K[8 + j * 3 + 2];
                d += s * WDV[i * 4 + j] * ISQ3;
            }
#pragma unroll
            for (int off = 16; off; off >>= 1) d += __shfl_xor_sync(0xffffffffu, d, off);
            if (lane == 0 && active) {
                d *= 0.11180339887498948f;               // 1/sqrt(80)
                float ex = __expf(d);
                g_ex[eg] = ex;
                atomicAdd(&g_z[sidx[le * 2 + 1]], ex);
            }
        }
        __syncthreads();
    }
}

// ---------------------------------------------------------------------------
// Kernel 2: alpha = sqrt(ex / z[rcv])  (in place into g_ex)
// ---------------------------------------------------------------------------
__global__ void k_alpha(const int* __restrict__ eidx, int E)
{
    int e = blockIdx.x * blockDim.x + threadIdx.x;
    if (e >= E) return;
    int rcv = eidx[E + e];
    g_ex[e] = sqrtf(__fdividef(g_ex[e], g_z[rcv]));
}

// ---------------------------------------------------------------------------
// Kernel 3: scatter-add with vector reductions (4 floats per red op)
// ---------------------------------------------------------------------------
__global__ void k_scatter(const int* __restrict__ eidx,
                          float* __restrict__ out, int E)
{
    int idx = blockIdx.x * blockDim.x + threadIdx.x;
    int e = idx / 10;
    int q = idx % 10;
    if (e >= E) return;
    int rcv = eidx[E + e];
    float a = g_ex[e];
    float4 v = *reinterpret_cast<const float4*>(&g_v[(size_t)e * 40 + q * 4]);
    float* dst = &out[(size_t)rcv * 40 + q * 4];
    asm volatile("red.global.add.v4.f32 [%0], {%1, %2, %3, %4};"
                 :: "l"(dst), "f"(a * v.x), "f"(a * v.y), "f"(a * v.z), "f"(a * v.w)
                 : "memory");
}

// ---------------------------------------------------------------------------
extern "C" void kernel_launch(void* const* d_in, const int* in_sizes, int n_in,
                              void* d_out, int out_size)
{
    const float* node_ft = (const float*)d_in[0];
    const int*   eidx    = (const int*)d_in[1];
    const float* edge_sh = (const float*)d_in[2];
    const float* edge_sc = (const float*)d_in[3];
    const float* wqs     = (const float*)d_in[4];
    const float* wqv     = (const float*)d_in[5];
    const float* fck_w1  = (const float*)d_in[6];
    const float* fck_w2  = (const float*)d_in[7];
    const float* fcv_w1  = (const float*)d_in[8];
    const float* fcv_w2  = (const float*)d_in[9];
    const float* wdot_s  = (const float*)d_in[10];
    const float* wdot_v  = (const float*)d_in[11];
    float* out = (float*)d_out;

    int N = in_sizes[0] / 40;
    int E = in_sizes[1] / 2;

    cudaFuncSetAttribute(k_edges, cudaFuncAttributeMaxDynamicSharedMemorySize, SMEM_BYTES);

    k_nodes<<<(N + 63) / 64, 64>>>(node_ft, wqs, wqv, out, N);
    k_edges<<<148, 256, SMEM_BYTES>>>(node_ft, eidx, edge_sh, edge_sc,
                                      fck_w1, fck_w2, fcv_w1, fcv_w2,
                                      wdot_s, wdot_v, E);
    k_alpha<<<(E + 255) / 256, 256>>>(eidx, E);
    k_scatter<<<((long long)E * 10 + 255) / 256, 256>>>(eidx, out, E);
}

// round 4
// speedup vs baseline: 1.2557x; 1.2557x over previous
#include <cuda_runtime.h>
#include <math.h>

#define N_MAX 10000
#define E_MAX 100000

typedef unsigned long long ull;

// Scratch (no cudaMalloc allowed)
__device__ float g_q[N_MAX * 20];         // per-node q: 8 scalar + 4*3 vector
__device__ float g_z[N_MAX];              // softmax denominator
__device__ float g_ex[E_MAX];             // per-edge exp(dot) -> later sqrt(alpha)
__device__ float g_v[(size_t)E_MAX * 40]; // per-edge v: 16 scalar + 8*3 vector

// ---- packed f32x2 helpers (sm_100+) ----
__device__ __forceinline__ ull ffma2(ull a, ull b, ull c) {
    ull d; asm("fma.rn.f32x2 %0, %1, %2, %3;" : "=l"(d) : "l"(a), "l"(b), "l"(c)); return d;
}
__device__ __forceinline__ ull fmul2(ull a, ull b) {
    ull d; asm("mul.rn.f32x2 %0, %1, %2;" : "=l"(d) : "l"(a), "l"(b)); return d;
}
__device__ __forceinline__ ull pack2(float a, float b) {
    ull r; asm("mov.b64 %0, {%1, %2};" : "=l"(r) : "f"(a), "f"(b)); return r;
}
__device__ __forceinline__ void unpack2(ull v, float& lo, float& hi) {
    asm("mov.b64 {%0, %1}, %2;" : "=f"(lo), "=f"(hi) : "l"(v));
}

// ---------------------------------------------------------------------------
// Kernel 0: per-node q projection, zero z and out
// ---------------------------------------------------------------------------
__global__ void __launch_bounds__(64) k_nodes(const float* __restrict__ node_ft,
                        const float* __restrict__ wqs,   // [16,8]
                        const float* __restrict__ wqv,   // [8,4]
                        float* __restrict__ out, int N)
{
    int n = blockIdx.x * blockDim.x + threadIdx.x;
    if (n >= N) return;
    const float* x = node_ft + (size_t)n * 40;
    float xs[16], xv[24];
#pragma unroll
    for (int i = 0; i < 16; i++) xs[i] = x[i];
#pragma unroll
    for (int i = 0; i < 24; i++) xv[i] = x[16 + i];

    const float s0 = 0.25f;                   // 1/sqrt(16)
    const float s1 = 0.35355339059327373f;    // 1/sqrt(8)
    float q[20];
#pragma unroll
    for (int o = 0; o < 8; o++) {
        float acc = 0.f;
#pragma unroll
        for (int i = 0; i < 16; i++) acc += xs[i] * wqs[i * 8 + o];
        q[o] = acc * s0;
    }
#pragma unroll
    for (int o = 0; o < 4; o++) {
#pragma unroll
        for (int c = 0; c < 3; c++) {
            float acc = 0.f;
#pragma unroll
            for (int i = 0; i < 8; i++) acc += xv[i * 3 + c] * wqv[i * 4 + o];
            q[8 + o * 3 + c] = acc * s1;
        }
    }
#pragma unroll
    for (int i = 0; i < 20; i++) g_q[(size_t)n * 20 + i] = q[i];
    g_z[n] = 0.f;
    float4 z4 = make_float4(0.f, 0.f, 0.f, 0.f);
#pragma unroll
    for (int i = 0; i < 10; i++)
        *reinterpret_cast<float4*>(&out[(size_t)n * 40 + i * 4]) = z4;
}

// ---------------------------------------------------------------------------
// Kernel 1: per-edge main work (R2 skeleton + FFMA2 edge-packed phase 2).
//   Block = 256 threads handles 8 edges; multiple blocks/SM for latency hiding.
// ---------------------------------------------------------------------------
__global__ void __launch_bounds__(256) k_edges(
    const float* __restrict__ node_ft,
    const int* __restrict__ eidx,            // [2,E] int32
    const float* __restrict__ edge_sh,       // [E,4]
    const float* __restrict__ edge_sc,       // [E,16]
    const float* __restrict__ fck_w1,        // [16,32]
    const float* __restrict__ fck_w2,        // [32,320]
    const float* __restrict__ fcv_w1,        // [16,32]
    const float* __restrict__ fcv_w2,        // [32,640]
    const float* __restrict__ wdot_s,        // [8,8]
    const float* __restrict__ wdot_v,        // [4,4]
    int E)
{
    // h stored edge-pair-packed: Hk_f[j*8 + e], viewed as ull pairs {e0,e1}..
    __shared__ ull  sh_hk[32 * 4];    // k-branch hidden acts, 8 edges packed
    __shared__ ull  sh_hv[32 * 4];    // v-branch
    __shared__ float sh_wk[8][320];
    __shared__ float sh_wv[8][640];
    __shared__ float sh_p[8][96];     // XS@0(16) XV@16(24) SHS@40 SHV@41(3) PSS@44(16) PVV@60(8) PXX@68(24)
    __shared__ float sh_k[8][20];     // k_s(8) + k_v(12)

    const int tid   = threadIdx.x;
    const int ebase = blockIdx.x * 8;

    // ---- Phase 1: hidden activations (512 tasks) ----
    float* Hk_f = (float*)sh_hk;
    float* Hv_f = (float*)sh_hv;
#pragma unroll
    for (int s = 0; s < 2; s++) {
        int task = tid + s * 256;
        int e  = task >> 6;
        int jj = task & 63;
        int eg = min(ebase + e, E - 1);
        const float* es = edge_sc + (size_t)eg * 16;
        const float* W1 = (jj < 32) ? fck_w1 : fcv_w1;
        int j = jj & 31;
        float acc = 0.f;
#pragma unroll
        for (int i = 0; i < 16; i++) acc += es[i] * W1[i * 32 + j];
        acc *= 0.25f;                                   // 1/sqrt(16)
        float h = acc / (1.f + expf(-acc));             // silu
        if (jj < 32) Hk_f[j * 8 + e] = h;
        else         Hv_f[j * 8 + e] = h;
    }
    __syncthreads();

    // ---- Phase 2: weight generation, FFMA2 edge-pair packed ----
    const float ISQ32 = 0.17677669529663687f;           // 1/sqrt(32)
    if (tid < 240) {
        const float* W2; float* OW; const ulonglong2* H2; int col, ncol;
        if (tid < 80) { W2 = fck_w2; OW = &sh_wk[0][0]; col = tid * 4;        ncol = 320; H2 = (const ulonglong2*)sh_hk; }
        else          { W2 = fcv_w2; OW = &sh_wv[0][0]; col = (tid - 80) * 4; ncol = 640; H2 = (const ulonglong2*)sh_hv; }

        ull acc[4][4];  // [col 0..3][edge-pair 0..3]
#pragma unroll
        for (int c = 0; c < 4; c++)
#pragma unroll
            for (int p = 0; p < 4; p++) acc[c][p] = 0ull;

#pragma unroll 2
        for (int j = 0; j < 32; j++) {
            float4 w = __ldg(reinterpret_cast<const float4*>(W2 + (size_t)j * ncol + col));
            ull wd[4] = { pack2(w.x, w.x), pack2(w.y, w.y), pack2(w.z, w.z), pack2(w.w, w.w) };
            ulonglong2 hA = H2[j * 2 + 0];   // edge pairs {0,1},{2,3}
            ulonglong2 hB = H2[j * 2 + 1];   // edge pairs {4,5},{6,7}
            ull hp[4] = { hA.x, hA.y, hB.x, hB.y };
#pragma unroll
            for (int c = 0; c < 4; c++) {
#pragma unroll
                for (int p = 0; p < 4; p++)
                    acc[c][p] = ffma2(hp[p], wd[c], acc[c][p]);
            }
        }
        ull sc = pack2(ISQ32, ISQ32);
#pragma unroll
        for (int c = 0; c < 4; c++) {
#pragma unroll
            for (int p = 0; p < 4; p++) {
                float lo, hi;
                unpack2(fmul2(acc[c][p], sc), lo, hi);
                OW[(size_t)(2 * p)     * ncol + col + c] = lo;
                OW[(size_t)(2 * p + 1) * ncol + col + c] = hi;
            }
        }
    }
    __syncthreads();

    // ---- Phase 3: warp per edge ----
    const float ISQ24 = 0.2041241452319315f;    // 1/sqrt(24)
    const float ISQ3  = 0.5773502691896258f;    // 1/sqrt(3)
    const float ISQ2  = 0.7071067811865476f;    // 1/sqrt(2)
    const int wid  = tid >> 5;
    const int lane = tid & 31;
    const int eg   = ebase + wid;
    const bool active = (eg < E);
    const int egc  = min(eg, E - 1);
    const int snd = eidx[egc];
    const int rcv = eidx[E + egc];
    const float* nf = node_ft + (size_t)snd * 40;
    const float shs  = edge_sh[(size_t)egc * 4 + 0];
    const float shv0 = edge_sh[(size_t)egc * 4 + 1];
    const float shv1 = edge_sh[(size_t)egc * 4 + 2];
    const float shv2 = edge_sh[(size_t)egc * 4 + 3];
    float* P = sh_p[wid];

    if (lane < 16) {
        float xs = nf[lane];
        P[lane]      = xs;
        P[44 + lane] = xs * shs;                    // p_ss
    } else if (lane < 24) {
        int i = lane - 16;
        float v0 = nf[16 + i * 3 + 0];
        float v1 = nf[16 + i * 3 + 1];
        float v2 = nf[16 + i * 3 + 2];
        P[16 + i * 3 + 0] = v0; P[16 + i * 3 + 1] = v1; P[16 + i * 3 + 2] = v2;
        P[60 + i] = (v0 * shv0 + v1 * shv1 + v2 * shv2) * ISQ3;       // p_vv
        P[68 + i * 3 + 0] = (v1 * shv2 - v2 * shv1) * ISQ2;           // cross/sqrt2
        P[68 + i * 3 + 1] = (v2 * shv0 - v0 * shv2) * ISQ2;
        P[68 + i * 3 + 2] = (v0 * shv1 - v1 * shv0) * ISQ2;
    } else if (lane == 24) {
        P[40] = shs; P[41] = shv0; P[42] = shv1; P[43] = shv2;
    }
    __syncwarp();

    const float* WK = sh_wk[wid];
    const float* WV = sh_wv[wid];
    float* K = sh_k[wid];

    // k_s (lanes 0..7), k_v (lanes 8..19)
    if (lane < 8) {
        int o = lane;
        float acc = 0.f;
#pragma unroll
        for (int i = 0; i < 16; i++) acc += P[44 + i] * WK[i * 8 + o];
#pragma unroll
        for (int i = 0; i < 8;  i++) acc += P[60 + i] * WK[128 + i * 8 + o];
        K[o] = acc * ISQ24;
    } else if (lane < 20) {
        int t = lane - 8; int o = t / 3; int c = t % 3;
        float a = 0.f, b = 0.f, cx = 0.f;
#pragma unroll
        for (int i = 0; i < 16; i++) a  += P[i]              * WK[192 + i * 4 + o];
#pragma unroll
        for (int i = 0; i < 8;  i++) b  += P[16 + i * 3 + c] * WK[256 + i * 4 + o];
#pragma unroll
        for (int i = 0; i < 8;  i++) cx += P[68 + i * 3 + c] * WK[288 + i * 4 + o];
        K[8 + t] = (P[41 + c] * a + P[40] * b + cx) * ISQ32;
    }

    // v_s (lanes 0..15)
    if (lane < 16) {
        int o = lane;
        float acc = 0.f;
#pragma unroll
        for (int i = 0; i < 16; i++) acc += P[44 + i] * WV[i * 16 + o];
#pragma unroll
        for (int i = 0; i < 8;  i++) acc += P[60 + i] * WV[256 + i * 16 + o];
        if (active) g_v[(size_t)eg * 40 + o] = acc * ISQ24;
    }
    // v_v: 24 comps. lanes 16..31 -> t=0..15, lanes 0..7 -> t=16..23
    {
        int t = (lane >= 16) ? (lane - 16) : (lane + 16);
        if (t < 24) {
            int o = t / 3, c = t % 3;
            float a = 0.f, b = 0.f, cx = 0.f;
#pragma unroll
            for (int i = 0; i < 16; i++) a  += P[i]              * WV[384 + i * 8 + o];
#pragma unroll
            for (int i = 0; i < 8;  i++) b  += P[16 + i * 3 + c] * WV[512 + i * 8 + o];
#pragma unroll
            for (int i = 0; i < 8;  i++) cx += P[68 + i * 3 + c] * WV[576 + i * 8 + o];
            float vv = (P[41 + c] * a + P[40] * b + cx) * ISQ32;
            if (active) g_v[(size_t)eg * 40 + 16 + t] = vv;
        }
    }
    __syncwarp();

    // dot(q[recv], k)
    const float* qr = g_q + (size_t)rcv * 20;
    float d = 0.f;
    {
        int term = lane;
        int i = term >> 3, j = term & 7;
        d += qr[i] * K[j] * wdot_s[i * 8 + j];
        term += 32; i = term >> 3; j = term & 7;
        d += qr[i] * K[j] * wdot_s[i * 8 + j];
    }
    if (lane < 16) {
        int i = lane >> 2, j = lane & 3;
        float s = qr[8 + i * 3 + 0] * K[8 + j * 3 + 0]
                + qr[8 + i * 3 + 1] * K[8 + j * 3 + 1]
                + qr[8 + i * 3 + 2] * K[8 + j * 3 + 2];
        d += s * wdot_v[i * 4 + j] * ISQ3;
    }
#pragma unroll
    for (int off = 16; off; off >>= 1) d += __shfl_xor_sync(0xffffffffu, d, off);
    if (lane == 0 && active) {
        d *= 0.11180339887498948f;                 // 1/sqrt(80)
        float ex = expf(d);
        g_ex[eg] = ex;
        atomicAdd(&g_z[rcv], ex);
    }
}

// ---------------------------------------------------------------------------
// Kernel 2: alpha = sqrt(ex / z[rcv])  (in place into g_ex)
// ---------------------------------------------------------------------------
__global__ void k_alpha(const int* __restrict__ eidx, int E)
{
    int e = blockIdx.x * blockDim.x + threadIdx.x;
    if (e >= E) return;
    int rcv = eidx[E + e];
    g_ex[e] = sqrtf(__fdividef(g_ex[e], g_z[rcv]));
}

// ---------------------------------------------------------------------------
// Kernel 3: scatter-add with vector reductions (4 floats per red op)
// ---------------------------------------------------------------------------
__global__ void k_scatter(const int* __restrict__ eidx,
                          float* __restrict__ out, int E)
{
    int idx = blockIdx.x * blockDim.x + threadIdx.x;
    int e = idx / 10;
    int q = idx % 10;
    if (e >= E) return;
    int rcv = eidx[E + e];
    float a = g_ex[e];
    float4 v = *reinterpret_cast<const float4*>(&g_v[(size_t)e * 40 + q * 4]);
    float* dst = &out[(size_t)rcv * 40 + q * 4];
    asm volatile("red.global.add.v4.f32 [%0], {%1, %2, %3, %4};"
                 :: "l"(dst), "f"(a * v.x), "f"(a * v.y), "f"(a * v.z), "f"(a * v.w)
                 : "memory");
}

// ---------------------------------------------------------------------------
extern "C" void kernel_launch(void* const* d_in, const int* in_sizes, int n_in,
                              void* d_out, int out_size)
{
    const float* node_ft = (const float*)d_in[0];
    const int*   eidx    = (const int*)d_in[1];
    const float* edge_sh = (const float*)d_in[2];
    const float* edge_sc = (const float*)d_in[3];
    const float* wqs     = (const float*)d_in[4];
    const float* wqv     = (const float*)d_in[5];
    const float* fck_w1  = (const float*)d_in[6];
    const float* fck_w2  = (const float*)d_in[7];
    const float* fcv_w1  = (const float*)d_in[8];
    const float* fcv_w2  = (const float*)d_in[9];
    const float* wdot_s  = (const float*)d_in[10];
    const float* wdot_v  = (const float*)d_in[11];
    float* out = (float*)d_out;

    int N = in_sizes[0] / 40;
    int E = in_sizes[1] / 2;

    k_nodes<<<(N + 63) / 64, 64>>>(node_ft, wqs, wqv, out, N);
    k_edges<<<(E + 7) / 8, 256>>>(node_ft, eidx, edge_sh, edge_sc,
                                  fck_w1, fck_w2, fcv_w1, fcv_w2,
                                  wdot_s, wdot_v, E);
    k_alpha<<<(E + 255) / 256, 256>>>(eidx, E);
    k_scatter<<<((long long)E * 10 + 255) / 256, 256>>>(eidx, out, E);
}